// round 17
// baseline (speedup 1.0000x reference)
#include <cuda_runtime.h>
#include <cuda_fp16.h>
#include <math.h>
#include <stdint.h>

#define DM 3072
#define BB 2
#define SSEQ 1024
#define NH 24
#define HD 128
#define MROWS (BB*SSEQ)   // 2048

// Scratch (device globals: no allocations allowed)
__device__ float  g_q[MROWS*DM];    // aliased as __half q-hat
__device__ __half g_xh[MROWS*DM];
__device__ __half g_kh[MROWS*DM];
__device__ __half g_vh[MROWS*DM];
__device__ __half g_aoh[MROWS*DM];
__device__ __half g_wqh[DM*DM];
__device__ __half g_wkh[DM*DM];
__device__ __half g_wvh[DM*DM];
__device__ __half g_woh[DM*DM];
__device__ float  g_cos[SSEQ*HD];
__device__ float  g_sin[SSEQ*HD];

__device__ __forceinline__ uint32_t smem_u32(const void* p) {
    uint32_t a;
    asm("{ .reg .u64 t; cvta.to.shared.u64 t, %1; cvt.u32.u64 %0, t; }"
        : "=r"(a) : "l"(p));
    return a;
}

__device__ __forceinline__ float fexp2(float x) {
    float y;
    asm("ex2.approx.f32 %0, %1;" : "=f"(y) : "f"(x));
    return y;
}

__device__ __forceinline__ uint32_t h2exp2_bits(uint32_t x) {
    uint32_t y;
    asm("ex2.approx.f16x2 %0, %1;" : "=r"(y) : "r"(x));
    return y;
}

__device__ __forceinline__ void mma_f16(float c[4],
    uint32_t a0, uint32_t a1, uint32_t a2, uint32_t a3,
    uint32_t b0, uint32_t b1)
{
    asm volatile(
        "mma.sync.aligned.m16n8k16.row.col.f32.f16.f16.f32 "
        "{%0,%1,%2,%3}, {%4,%5,%6,%7}, {%8,%9}, {%0,%1,%2,%3};"
        : "+f"(c[0]), "+f"(c[1]), "+f"(c[2]), "+f"(c[3])
        : "r"(a0), "r"(a1), "r"(a2), "r"(a3), "r"(b0), "r"(b1));
}

__device__ __forceinline__ void ldsm_x4(
    uint32_t& r0, uint32_t& r1, uint32_t& r2, uint32_t& r3, uint32_t addr)
{
    asm volatile("ldmatrix.sync.aligned.m8n8.x4.shared.b16 {%0,%1,%2,%3}, [%4];"
        : "=r"(r0), "=r"(r1), "=r"(r2), "=r"(r3) : "r"(addr));
}

__device__ __forceinline__ void ldsm_x4_t(
    uint32_t& r0, uint32_t& r1, uint32_t& r2, uint32_t& r3, uint32_t addr)
{
    asm volatile("ldmatrix.sync.aligned.m8n8.x4.trans.shared.b16 {%0,%1,%2,%3}, [%4];"
        : "=r"(r0), "=r"(r1), "=r"(r2), "=r"(r3) : "r"(addr));
}

__device__ __forceinline__ void cp_async16(uint32_t saddr, const void* gptr) {
    asm volatile("cp.async.cg.shared.global [%0], [%1], 16;"
        :: "r"(saddr), "l"(gptr) : "memory");
}
#define CP_COMMIT() asm volatile("cp.async.commit_group;" ::: "memory")
#define CP_WAIT2()  asm volatile("cp.async.wait_group 2;" ::: "memory")
#define CP_WAIT1()  asm volatile("cp.async.wait_group 1;" ::: "memory")

__device__ __forceinline__ void red_add_f32(float* p, float v) {
    asm volatile("red.global.add.f32 [%0], %1;" :: "l"(p), "f"(v) : "memory");
}

// ---------------------------------------------------------------------------
// Support kernels
// ---------------------------------------------------------------------------
__global__ __launch_bounds__(256) void cvt_f32_f16(
    const float* __restrict__ src, __half* __restrict__ dst, int n4h)
{
    int i = blockIdx.x * blockDim.x + threadIdx.x;
    if (i < n4h) {
        float4 v0 = ((const float4*)src)[i];
        float4 v1 = ((const float4*)src)[i + n4h];
        __half2 a0 = __floats2half2_rn(v0.x, v0.y);
        __half2 a1 = __floats2half2_rn(v0.z, v0.w);
        __half2 b0 = __floats2half2_rn(v1.x, v1.y);
        __half2 b1 = __floats2half2_rn(v1.z, v1.w);
        uint2 o0 = {*(uint32_t*)&a0, *(uint32_t*)&a1};
        uint2 o1 = {*(uint32_t*)&b0, *(uint32_t*)&b1};
        ((uint2*)dst)[i]       = o0;
        ((uint2*)dst)[i + n4h] = o1;
    }
}

// 4 matrices via blockIdx.y; ILP-2 within each
__global__ __launch_bounds__(256) void cvt4_f32_f16(
    const float* __restrict__ s0, const float* __restrict__ s1,
    const float* __restrict__ s2, const float* __restrict__ s3,
    __half* __restrict__ d0, __half* __restrict__ d1,
    __half* __restrict__ d2, __half* __restrict__ d3, int n4h)
{
    const int which = blockIdx.y;
    const float* s = (which == 0) ? s0 : (which == 1) ? s1 : (which == 2) ? s2 : s3;
    __half* d      = (which == 0) ? d0 : (which == 1) ? d1 : (which == 2) ? d2 : d3;
    int i = blockIdx.x * blockDim.x + threadIdx.x;
    if (i < n4h) {
        float4 v0 = ((const float4*)s)[i];
        float4 v1 = ((const float4*)s)[i + n4h];
        __half2 a0 = __floats2half2_rn(v0.x, v0.y);
        __half2 a1 = __floats2half2_rn(v0.z, v0.w);
        __half2 b0 = __floats2half2_rn(v1.x, v1.y);
        __half2 b1 = __floats2half2_rn(v1.z, v1.w);
        uint2 o0 = {*(uint32_t*)&a0, *(uint32_t*)&a1};
        uint2 o1 = {*(uint32_t*)&b0, *(uint32_t*)&b1};
        ((uint2*)d)[i]       = o0;
        ((uint2*)d)[i + n4h] = o1;
    }
}

__global__ __launch_bounds__(256) void zero_f32(float* __restrict__ p, int n4)
{
    int i = blockIdx.x * blockDim.x + threadIdx.x;
    if (i < n4) {
        float4 z = {0.f, 0.f, 0.f, 0.f};
        ((float4*)p)[i] = z;
    }
}

__global__ __launch_bounds__(128) void rope_tab_kernel(
    const float* __restrict__ rope, float* __restrict__ ct, float* __restrict__ st)
{
    int i = blockIdx.x * 128 + threadIdx.x;
    float sn, cs;
    sincosf(rope[i], &sn, &cs);
    ct[i] = cs;
    st[i] = sn;
}

// ---------------------------------------------------------------------------
// fp16 GEMM, cp.async 4-stage pipeline (R12/R16, best), one sync per k-tile.
// !REDUCE: wsel 0/1 outputs get fused RMSNorm+RoPE epilogue (tile = one head),
//          wsel 2 writes fp16 directly.
// REDUCE : fp32 red.add epilogue (k-split Wo).
// ---------------------------------------------------------------------------
#define STAGEB 20480
#define NSTAGE 4
#define GEMM_SMEM (NSTAGE * STAGEB)   // 81920
#define XS_STRIDE 132

template<bool REDUCE>
__global__ __launch_bounds__(256, 2) void f16_gemm_kernel(
    const __half* __restrict__ X,
    const __half* __restrict__ Wa, const __half* __restrict__ Wb, const __half* __restrict__ Wc,
    __half* __restrict__ Yq, __half* __restrict__ Yk, __half* __restrict__ Yv,
    float* __restrict__ Yred,
    const float* __restrict__ nqw, const float* __restrict__ nkw,
    const float* __restrict__ ct, const float* __restrict__ st)
{
    extern __shared__ char smraw[];
    const uint32_t smb = smem_u32(smraw);

    const int t    = threadIdx.x;
    const int lane = t & 31;
    const int w    = t >> 5;
    const int warp_m = (w >> 1) * 32;
    const int warp_n = (w & 1) * 64;
    const int bx   = blockIdx.x;
    const int wsel = bx / 24;
    const __half* W = (wsel == 0) ? Wa : ((wsel == 1) ? Wb : Wc);
    const int bm = blockIdx.y * 128;
    const int bn = (bx - wsel * 24) * 128;

    const int nkt = (DM / 32) / gridDim.z;
    const int kh0 = blockIdx.z * nkt * 32;

    const int arow = t >> 1;
    const int kh16 = (t & 1) * 16;
    const __half* xp = X + (size_t)(bm + arow) * DM + kh0 + kh16;
    const __half* wp = W + (size_t)(bn + arow) * DM + kh0 + kh16;
    const uint32_t srow = (uint32_t)arow * 80u + (uint32_t)kh16 * 2u;

    const int l7 = lane & 7;
    const int aArow = warp_m + ((lane >> 3) & 1) * 8 + l7;
    const int aAkh  = (lane >> 4) * 8;
    uint32_t offA[2];
    #pragma unroll
    for (int mi = 0; mi < 2; mi++)
        offA[mi] = (uint32_t)(aArow + mi * 16) * 80u + (uint32_t)aAkh * 2u;
    const int aBn  = warp_n + (lane >> 4) * 8 + l7;
    const int aBkh = ((lane >> 3) & 1) * 8;
    uint32_t offB[4];
    #pragma unroll
    for (int np = 0; np < 4; np++)
        offB[np] = 10240u + (uint32_t)(aBn + np * 16) * 80u + (uint32_t)aBkh * 2u;

    float c[2][8][4];
    #pragma unroll
    for (int mi = 0; mi < 2; mi++)
        #pragma unroll
        for (int ni = 0; ni < 8; ni++)
            #pragma unroll
            for (int j = 0; j < 4; j++) c[mi][ni][j] = 0.f;

    const int qd = lane >> 2;
    const int qk = lane & 3;

    #define ISSUE(kt_, buf_) do { \
        const uint32_t sa = smb + (uint32_t)(buf_) * STAGEB + srow; \
        const __half* xg = xp + (kt_) * 32; \
        const __half* wg = wp + (kt_) * 32; \
        cp_async16(sa,           xg); \
        cp_async16(sa + 16u,     xg + 8); \
        cp_async16(sa + 10240u,      wg); \
        cp_async16(sa + 10240u + 16u, wg + 8); \
    } while (0)

    ISSUE(0, 0); CP_COMMIT();
    ISSUE(1, 1); CP_COMMIT();
    ISSUE(2, 2); CP_COMMIT();

    for (int kt = 0; kt < nkt; kt++) {
        const int buf = kt & 3;
        CP_WAIT2();
        __syncthreads();

        const int nk = kt + 3;
        if (nk < nkt) {
            ISSUE(nk, nk & 3);
        }
        CP_COMMIT();

        const uint32_t stg = smb + (uint32_t)buf * STAGEB;
        #pragma unroll
        for (int ks = 0; ks < 2; ks++) {
            const uint32_t koff = (uint32_t)ks * 32u;
            uint32_t a[2][4];
            ldsm_x4(a[0][0], a[0][1], a[0][2], a[0][3], stg + offA[0] + koff);
            ldsm_x4(a[1][0], a[1][1], a[1][2], a[1][3], stg + offA[1] + koff);
            #pragma unroll
            for (int np = 0; np < 4; np++) {
                uint32_t b0, b1, b2, b3;
                ldsm_x4(b0, b1, b2, b3, stg + offB[np] + koff);
                mma_f16(c[0][2*np],   a[0][0], a[0][1], a[0][2], a[0][3], b0, b1);
                mma_f16(c[1][2*np],   a[1][0], a[1][1], a[1][2], a[1][3], b0, b1);
                mma_f16(c[0][2*np+1], a[0][0], a[0][1], a[0][2], a[0][3], b2, b3);
                mma_f16(c[1][2*np+1], a[1][0], a[1][1], a[1][2], a[1][3], b2, b3);
            }
        }
    }
    #undef ISSUE

    if (REDUCE) {
        float* Y = Yred;
        #pragma unroll
        for (int mi = 0; mi < 2; mi++) {
            #pragma unroll
            for (int ni = 0; ni < 8; ni++) {
                const int row = bm + warp_m + mi*16 + qd;
                const int col = bn + warp_n + ni*8 + qk*2;
                float* p0 = Y + (size_t)row * DM + col;
                float* p1 = Y + (size_t)(row + 8) * DM + col;
                red_add_f32(p0,     c[mi][ni][0]);
                red_add_f32(p0 + 1, c[mi][ni][1]);
                red_add_f32(p1,     c[mi][ni][2]);
                red_add_f32(p1 + 1, c[mi][ni][3]);
            }
        }
    } else if (wsel == 2) {
        #pragma unroll
        for (int mi = 0; mi < 2; mi++) {
            #pragma unroll
            for (int ni = 0; ni < 8; ni++) {
                const int row = bm + warp_m + mi*16 + qd;
                const int col = bn + warp_n + ni*8 + qk*2;
                __half2 h0 = __floats2half2_rn(c[mi][ni][0], c[mi][ni][1]);
                __half2 h1 = __floats2half2_rn(c[mi][ni][2], c[mi][ni][3]);
                *(__half2*)(Yv + (size_t)row * DM + col)       = h0;
                *(__half2*)(Yv + (size_t)(row + 8) * DM + col) = h1;
            }
        }
    } else {
        // ---- fused RMSNorm + RoPE epilogue (tile N-range == one head) ----
        __syncthreads();   // mainloop smem reads done; region reusable
        float* Xs = (float*)smraw;                      // [128][132] fp32
        float* SR = (float*)(smraw + 128*XS_STRIDE*4);  // [2][128]

        // per-thread row partial sums of squares (16 cols per row)
        #pragma unroll
        for (int mi = 0; mi < 2; mi++) {
            float s0 = 0.f, s1 = 0.f;
            #pragma unroll
            for (int ni = 0; ni < 8; ni++) {
                s0 += c[mi][ni][0]*c[mi][ni][0] + c[mi][ni][1]*c[mi][ni][1];
                s1 += c[mi][ni][2]*c[mi][ni][2] + c[mi][ni][3]*c[mi][ni][3];
            }
            s0 += __shfl_xor_sync(0xffffffffu, s0, 1);
            s0 += __shfl_xor_sync(0xffffffffu, s0, 2);
            s1 += __shfl_xor_sync(0xffffffffu, s1, 1);
            s1 += __shfl_xor_sync(0xffffffffu, s1, 2);
            if (qk == 0) {
                SR[(w & 1) * 128 + warp_m + mi*16 + qd]     = s0;
                SR[(w & 1) * 128 + warp_m + mi*16 + qd + 8] = s1;
            }
        }
        __syncthreads();

        const float* wn = wsel ? nkw : nqw;
        #pragma unroll
        for (int mi = 0; mi < 2; mi++) {
            const int r0 = warp_m + mi*16 + qd;
            const int r1 = r0 + 8;
            const float rs0 = rsqrtf((SR[r0] + SR[128 + r0]) * (1.f/128.f) + 1e-6f);
            const float rs1 = rsqrtf((SR[r1] + SR[128 + r1]) * (1.f/128.f) + 1e-6f);
            #pragma unroll
            for (int ni = 0; ni < 8; ni++) {
                const int col = warp_n + ni*8 + qk*2;
                const float w0 = wn[col], w1 = wn[col + 1];
                float2 v0 = {c[mi][ni][0] * rs0 * w0, c[mi][ni][1] * rs0 * w1};
                float2 v1 = {c[mi][ni][2] * rs1 * w0, c[mi][ni][3] * rs1 * w1};
                *(float2*)&Xs[r0 * XS_STRIDE + col] = v0;
                *(float2*)&Xs[r1 * XS_STRIDE + col] = v1;
            }
        }
        __syncthreads();

        __half* dst = wsel ? Yk : Yq;
        #pragma unroll
        for (int mi = 0; mi < 2; mi++) {
            #pragma unroll
            for (int rr = 0; rr < 2; rr++) {
                const int row = warp_m + mi*16 + qd + rr*8;
                const int s   = (bm + row) & (SSEQ - 1);
                #pragma unroll
                for (int ni = 0; ni < 8; ni++) {
                    const int col = warp_n + ni*8 + qk*2;
                    const int pc  = col ^ 64;
                    float x0 = Xs[row * XS_STRIDE + col];
                    float x1 = Xs[row * XS_STRIDE + col + 1];
                    float p0 = Xs[row * XS_STRIDE + pc];
                    float p1 = Xs[row * XS_STRIDE + pc + 1];
                    float rr0 = (col < 64) ? -p0 : p0;
                    float rr1 = (col < 64) ? -p1 : p1;
                    float2 csv = *(const float2*)(ct + s * HD + col);
                    float2 snv = *(const float2*)(st + s * HD + col);
                    __half2 hv = __floats2half2_rn(x0 * csv.x + rr0 * snv.x,
                                                   x1 * csv.y + rr1 * snv.y);
                    *(__half2*)(dst + (size_t)(bm + row) * DM + bn + col) = hv;
                }
            }
        }
    }
}

// ---------------------------------------------------------------------------
// fp16 flash attention (R16, best): FA2 register softmax, cp.async
// double-buffered K/V, hoisted Q fragments, Q-smem reuse, 3 CTAs/SM.
// ---------------------------------------------------------------------------
#define STH 136
#define STB (STH*2)
#define ATT_SMEM (4 * 64 * STB)   // 69632

__global__ __launch_bounds__(128, 3) void attn_kernel(
    const __half* __restrict__ Q, const __half* __restrict__ K,
    const __half* __restrict__ V, __half* __restrict__ O)
{
    extern __shared__ char smraw[];
    __half* Qh = (__half*)smraw;
    const uint32_t sQ = smem_u32(Qh);
    const uint32_t sB0 = sQ;
    const uint32_t sB1 = sQ + 64u * STB;
    const uint32_t sB2 = sQ + 128u * STB;
    const uint32_t sB3 = sQ + 192u * STB;

    const int t    = threadIdx.x;
    const int lane = t & 31;
    const int w    = t >> 5;
    const int qd   = lane >> 2;
    const int qk   = lane & 3;
    const int wm   = w * 16;

    const int qt = blockIdx.x;
    const int bh = blockIdx.y;
    const int b  = bh / NH;
    const int h  = bh % NH;
    const size_t base = (size_t)b * SSEQ * DM + (size_t)h * HD;
    const __half* qb = Q + base;
    const __half* kb = K + base;
    const __half* vb = V + base;
    const int q0 = qt * 64;

    const int l7   = lane & 7;
    const int arow = ((lane >> 3) & 1) * 8 + l7;
    const int akh  = (lane >> 4) * 8;
    const uint32_t aQ = sQ + (uint32_t)(wm + arow) * STB + (uint32_t)akh * 2u;
    const int bnr  = (lane >> 4) * 8 + l7;
    const int bkh  = ((lane >> 3) & 1) * 8;
    const uint32_t fK0 = sB0 + (uint32_t)bnr * STB + (uint32_t)bkh * 2u;
    const uint32_t fK1 = sB1 + (uint32_t)bnr * STB + (uint32_t)bkh * 2u;
    const uint32_t voff = (uint32_t)arow * STB + (uint32_t)((lane >> 4) * 8) * 2u;
    const uint32_t fV0 = sB2 + voff;
    const uint32_t fV1 = sB3 + voff;

    #define ATT_ISSUE(kt_, kbuf_, vbuf_) do { \
        const int k0_ = (kt_) * 64; \
        _Pragma("unroll") \
        for (int it = 0; it < 8; it++) { \
            const int f   = t + it * 128; \
            const int row = f >> 4; \
            const int ch  = f & 15; \
            const size_t g = (size_t)(k0_ + row) * DM + ch * 8; \
            const uint32_t so = (uint32_t)row * STB + (uint32_t)ch * 16u; \
            cp_async16((kbuf_) + so, kb + g); \
            cp_async16((vbuf_) + so, vb + g); \
        } \
    } while (0)

    #pragma unroll
    for (int it = 0; it < 8; it++) {
        const int f   = t + it * 128;
        const int row = f >> 4;
        const int c8  = (f & 15) * 8;
        uint4 u = *(const uint4*)(qb + (size_t)(q0 + row) * DM + c8);
        *(uint4*)(Qh + row * STH + c8) = u;
    }
    __syncthreads();

    uint32_t qf[8][4];
    #pragma unroll
    for (int ks = 0; ks < 8; ks++)
        ldsm_x4(qf[ks][0], qf[ks][1], qf[ks][2], qf[ks][3],
                aQ + (uint32_t)ks * 32u);
    __syncthreads();

    ATT_ISSUE(0, sB0, sB2); CP_COMMIT();
    ATT_ISSUE(1, sB1, sB3); CP_COMMIT();

    float o[16][4];
    #pragma unroll
    for (int ni = 0; ni < 16; ni++)
        #pragma unroll
        for (int j = 0; j < 4; j++) o[ni][j] = 0.f;

    float m0 = -1e30f, m1 = -1e30f, l0 = 0.f, l1 = 0.f;
    const float scale2 = 0.12751744f;

    for (int kt = 0; kt < 16; kt++) {
        CP_WAIT1();
        __syncthreads();

        const uint32_t fK = (kt & 1) ? fK1 : fK0;
        const uint32_t fV = (kt & 1) ? fV1 : fV0;

        float cs[8][4];
        #pragma unroll
        for (int ni = 0; ni < 8; ni++)
            #pragma unroll
            for (int j = 0; j < 4; j++) cs[ni][j] = 0.f;

        #pragma unroll
        for (int ks = 0; ks < 8; ks++) {
            const uint32_t koff = (uint32_t)ks * 32u;
            #pragma unroll
            for (int p = 0; p < 4; p++) {
                uint32_t b0, b1, b2, b3;
                ldsm_x4(b0, b1, b2, b3, fK + (uint32_t)(p * 16) * STB + koff);
                mma_f16(cs[2*p],   qf[ks][0], qf[ks][1], qf[ks][2], qf[ks][3], b0, b1);
                mma_f16(cs[2*p+1], qf[ks][0], qf[ks][1], qf[ks][2], qf[ks][3], b2, b3);
            }
        }
        #pragma unroll
        for (int ni = 0; ni < 8; ni++) {
            cs[ni][0] *= scale2; cs[ni][1] *= scale2;
            cs[ni][2] *= scale2; cs[ni][3] *= scale2;
        }

        float t0 = -1e30f, t1 = -1e30f;
        #pragma unroll
        for (int ni = 0; ni < 8; ni++) {
            t0 = fmaxf(t0, fmaxf(cs[ni][0], cs[ni][1]));
            t1 = fmaxf(t1, fmaxf(cs[ni][2], cs[ni][3]));
        }
        t0 = fmaxf(t0, __shfl_xor_sync(0xffffffffu, t0, 1));
        t0 = fmaxf(t0, __shfl_xor_sync(0xffffffffu, t0, 2));
        t1 = fmaxf(t1, __shfl_xor_sync(0xffffffffu, t1, 1));
        t1 = fmaxf(t1, __shfl_xor_sync(0xffffffffu, t1, 2));
        const float mn0 = fmaxf(m0, t0);
        const float mn1 = fmaxf(m1, t1);
        const float al0 = fexp2(m0 - mn0);
        const float al1 = fexp2(m1 - mn1);

        uint32_t plo[8], phi[8];
        float ps0 = 0.f, ps1 = 0.f;
        #pragma unroll
        for (int ni = 0; ni < 8; ni++) {
            __half2 d0 = __floats2half2_rn(cs[ni][0] - mn0, cs[ni][1] - mn0);
            __half2 d1 = __floats2half2_rn(cs[ni][2] - mn1, cs[ni][3] - mn1);
            plo[ni] = h2exp2_bits(*(uint32_t*)&d0);
            phi[ni] = h2exp2_bits(*(uint32_t*)&d1);
            __half2 p0 = *(__half2*)&plo[ni];
            __half2 p1 = *(__half2*)&phi[ni];
            ps0 += __low2float(p0) + __high2float(p0);
            ps1 += __low2float(p1) + __high2float(p1);
        }
        ps0 += __shfl_xor_sync(0xffffffffu, ps0, 1);
        ps0 += __shfl_xor_sync(0xffffffffu, ps0, 2);
        ps1 += __shfl_xor_sync(0xffffffffu, ps1, 1);
        ps1 += __shfl_xor_sync(0xffffffffu, ps1, 2);
        l0 = l0 * al0 + ps0;
        l1 = l1 * al1 + ps1;
        m0 = mn0;
        m1 = mn1;

        #pragma unroll
        for (int ni = 0; ni < 16; ni++) {
            o[ni][0] *= al0; o[ni][1] *= al0;
            o[ni][2] *= al1; o[ni][3] *= al1;
        }

        #pragma unroll
        for (int kc = 0; kc < 4; kc++) {
            const uint32_t a0 = plo[2*kc],   a1 = phi[2*kc];
            const uint32_t a2 = plo[2*kc+1], a3 = phi[2*kc+1];
            const uint32_t vro = (uint32_t)(kc * 16) * STB;
            #pragma unroll
            for (int np = 0; np < 8; np++) {
                uint32_t b0, b1, b2, b3;
                ldsm_x4_t(b0, b1, b2, b3, fV + vro + (uint32_t)np * 32u);
                mma_f16(o[2*np],   a0, a1, a2, a3, b0, b1);
                mma_f16(o[2*np+1], a0, a1, a2, a3, b2, b3);
            }
        }

        __syncthreads();
        if (kt + 2 < 16) {
            if (kt & 1) { ATT_ISSUE(kt + 2, sB1, sB3); }
            else        { ATT_ISSUE(kt + 2, sB0, sB2); }
        }
        CP_COMMIT();
    }
    #undef ATT_ISSUE

    const float inv0 = 1.f / l0;
    const float inv1 = 1.f / l1;
    #pragma unroll
    for (int ni = 0; ni < 16; ni++) {
        const int col = ni * 8 + 2 * qk;
        __half2 h0 = __floats2half2_rn(o[ni][0] * inv0, o[ni][1] * inv0);
        __half2 h1 = __floats2half2_rn(o[ni][2] * inv1, o[ni][3] * inv1);
        *(__half2*)(O + base + (size_t)(q0 + wm + qd)     * DM + col) = h0;
        *(__half2*)(O + base + (size_t)(q0 + wm + qd + 8) * DM + col) = h1;
    }
}

// ---------------------------------------------------------------------------
extern "C" void kernel_launch(void* const* d_in, const int* in_sizes, int n_in,
                              void* d_out, int out_size)
{
    const float* hidden = (const float*)d_in[0];
    const float* rope   = (const float*)d_in[1];
    const float* Wq     = (const float*)d_in[2];
    const float* Wk     = (const float*)d_in[3];
    const float* Wv     = (const float*)d_in[4];
    const float* Wo     = (const float*)d_in[5];
    const float* nqw    = (const float*)d_in[6];
    const float* nkw    = (const float*)d_in[7];
    float* out = (float*)d_out;

    float *qf, *ct, *st;
    __half *xh, *kh, *vh, *aoh, *wqh, *wkh, *wvh, *woh;
    cudaGetSymbolAddress((void**)&qf,  g_q);
    cudaGetSymbolAddress((void**)&xh,  g_xh);
    cudaGetSymbolAddress((void**)&kh,  g_kh);
    cudaGetSymbolAddress((void**)&vh,  g_vh);
    cudaGetSymbolAddress((void**)&aoh, g_aoh);
    cudaGetSymbolAddress((void**)&wqh, g_wqh);
    cudaGetSymbolAddress((void**)&wkh, g_wkh);
    cudaGetSymbolAddress((void**)&wvh, g_wvh);
    cudaGetSymbolAddress((void**)&woh, g_woh);
    cudaGetSymbolAddress((void**)&ct,  g_cos);
    cudaGetSymbolAddress((void**)&st,  g_sin);
    __half* qh = (__half*)qf;

    const int nX4 = MROWS * DM / 4;
    const int nW4h = DM * DM / 8;
    zero_f32<<<(nX4 + 255) / 256, 256>>>(out, nX4);
    rope_tab_kernel<<<SSEQ, 128>>>(rope, ct, st);
    cvt_f32_f16<<<(nX4/2 + 255) / 256, 256>>>(hidden, xh, nX4/2);
    cvt4_f32_f16<<<dim3((nW4h + 255) / 256, 4), 256>>>(Wq, Wk, Wv, Wo,
                                                       wqh, wkh, wvh, woh, nW4h);

    cudaFuncSetAttribute(f16_gemm_kernel<false>, cudaFuncAttributeMaxDynamicSharedMemorySize, GEMM_SMEM);
    cudaFuncSetAttribute(f16_gemm_kernel<true>,  cudaFuncAttributeMaxDynamicSharedMemorySize, GEMM_SMEM);
    cudaFuncSetAttribute(attn_kernel, cudaFuncAttributeMaxDynamicSharedMemorySize, ATT_SMEM);

    // Fused QKV projection + RMSNorm + RoPE: writes q-hat/k-hat/v fp16
    f16_gemm_kernel<false><<<dim3(72, 16, 1), 256, GEMM_SMEM>>>(
        xh, wqh, wkh, wvh, qh, kh, vh, nullptr, nqw, nkw, ct, st);

    attn_kernel<<<dim3(SSEQ/64, BB*NH), 128, ATT_SMEM>>>(qh, kh, vh, aoh);

    // Output projection, k-split 3, atomic-add epilogue
    f16_gemm_kernel<true><<<dim3(24, 16, 3), 256, GEMM_SMEM>>>(
        aoh, woh, woh, woh, nullptr, nullptr, nullptr, out, nqw, nkw, ct, st);
}